// round 16
// baseline (speedup 1.0000x reference)
#include <cuda_runtime.h>
#include <cuda_fp16.h>
#include <cstdint>
#include <math.h>

// ---------------------------------------------------------------------------
// Problem constants
// ---------------------------------------------------------------------------
#define BATCH 4
#define SEQ   2048
#define FDIM  1024
#define DKDIM 1024

// ---------------------------------------------------------------------------
// fp16 mma.sync GEMM tiling: CTA 128x128, warp 64x32, BK=64, 3 stages, 2 CTA/SM
// ---------------------------------------------------------------------------
#define BM 128
#define BN 128
#define BK 64
#define STAGES 3
#define GEMM_THREADS 256

#define ROWH 72
#define A_STAGE_HALVES (BM * ROWH)
#define B_STAGE_HALVES (BN * ROWH)
#define STAGE_HALVES   (A_STAGE_HALVES + B_STAGE_HALVES)
#define GEMM_SMEM      (STAGES * STAGE_HALVES * 2)   // 110,592 B

// GEMM4 (trans-B) layout: B tile kept [K,N] with padded rows
#define B4_ROWH 136
#define B4_STAGE_HALVES (BK * B4_ROWH)               // 8704
#define STAGE4_HALVES   (A_STAGE_HALVES + B4_STAGE_HALVES)
#define GEMM4_SMEM      (STAGES * STAGE4_HALVES * 2) // 107,520 B

#define VSCALE 64.0f
#define MTILES (SEQ / BM)

// ---------------------------------------------------------------------------
// Scratch (device globals — no dynamic allocation allowed)
// ---------------------------------------------------------------------------
__device__ __half g_gA  [(size_t)2 * FDIM * DKDIM];          // slot0: Wk, slot1: Wo^T
__device__ __half g_gB  [(size_t)2 * FDIM * DKDIM];          // slot0: Wq, slot1: Wv
__device__ __half g_mb  [(size_t)2 * DKDIM * FDIM];          // slot0: M'=WkWq^T, slot1: W'^T
__device__ __half g_qv  [(size_t)BATCH * SEQ * 2 * DKDIM];   // [qm | vw] in N
__device__ __half g_sc  [(size_t)BATCH * SEQ * SEQ];         // exp(scores)
__device__ float  g_bias2[(size_t)2 * DKDIM];                // 0 | b'=bv@Wo
__device__ float  g_w1  [FDIM];                              // Wq @ bk
__device__ float  g_w2  [FDIM];                              // Wk @ bq
__device__ float  g_c   [1];                                 // bq . bk
__device__ float  g_u   [(size_t)BATCH * SEQ];               // x.w1 + c
__device__ float  g_v   [(size_t)BATCH * SEQ];               // x.w2
__device__ float  g_part[(size_t)BATCH * MTILES * SEQ];
__device__ float  g_invcs[(size_t)BATCH * SEQ];              // VSCALE / colsum

// ---------------------------------------------------------------------------
// Helpers
// ---------------------------------------------------------------------------
__device__ __forceinline__ uint32_t smem_u32(const void* p) {
    uint32_t a;
    asm("{ .reg .u64 t; cvta.to.shared.u64 t, %1; cvt.u32.u64 %0, t; }" : "=r"(a) : "l"(p));
    return a;
}
__device__ __forceinline__ void cp_async16(uint32_t dst, const void* src) {
    asm volatile("cp.async.cg.shared.global [%0], [%1], 16;" :: "r"(dst), "l"(src) : "memory");
}
__device__ __forceinline__ void cp_commit() {
    asm volatile("cp.async.commit_group;" ::: "memory");
}
__device__ __forceinline__ void cp_wait_1() {
    asm volatile("cp.async.wait_group 1;" ::: "memory");
}
__device__ __forceinline__ void ldmatrix_x4(uint32_t* r, uint32_t addr) {
    asm volatile("ldmatrix.sync.aligned.m8n8.x4.shared.b16 {%0,%1,%2,%3}, [%4];"
                 : "=r"(r[0]), "=r"(r[1]), "=r"(r[2]), "=r"(r[3]) : "r"(addr));
}
__device__ __forceinline__ void ldmatrix_x4_trans(uint32_t* r, uint32_t addr) {
    asm volatile("ldmatrix.sync.aligned.m8n8.x4.trans.shared.b16 {%0,%1,%2,%3}, [%4];"
                 : "=r"(r[0]), "=r"(r[1]), "=r"(r[2]), "=r"(r[3]) : "r"(addr));
}
__device__ __forceinline__ void mma_f16(float* d, const uint32_t* a,
                                        uint32_t b0, uint32_t b1) {
    asm volatile(
        "mma.sync.aligned.m16n8k16.row.col.f32.f16.f16.f32 "
        "{%0,%1,%2,%3}, {%4,%5,%6,%7}, {%8,%9}, {%0,%1,%2,%3};"
        : "+f"(d[0]), "+f"(d[1]), "+f"(d[2]), "+f"(d[3])
        : "r"(a[0]), "r"(a[1]), "r"(a[2]), "r"(a[3]), "r"(b0), "r"(b1));
}
// load 8 fp32, convert RN to 8 fp16, store 16B to smem
__device__ __forceinline__ void ldg_f32_sts_h8(uint32_t dst, const float* src) {
    float4 p0 = *(const float4*)src;
    float4 p1 = *(const float4*)(src + 4);
    float4 outv;
    __half2* op = (__half2*)&outv;
    op[0] = __floats2half2_rn(p0.x, p0.y);
    op[1] = __floats2half2_rn(p0.z, p0.w);
    op[2] = __floats2half2_rn(p1.x, p1.y);
    op[3] = __floats2half2_rn(p1.z, p1.w);
    asm volatile("st.shared.v4.b32 [%0], {%1,%2,%3,%4};"
                 :: "r"(dst), "r"(((uint32_t*)&outv)[0]), "r"(((uint32_t*)&outv)[1]),
                    "r"(((uint32_t*)&outv)[2]), "r"(((uint32_t*)&outv)[3]) : "memory");
}

// ---------------------------------------------------------------------------
// fp16 tensor-core GEMM:  C = op(alpha * A * B^T + bias)
//   a_f32/b_f32: operand is fp32 in gmem; loader converts inline (RN) to fp16.
//   mode 0: plain; mode 1: C = exp((acc + u_m + v_n) * alpha), col sums -> part
// ---------------------------------------------------------------------------
__global__ void __launch_bounds__(GEMM_THREADS, 2)
gemm_f16_kernel(const void* __restrict__ Av, const void* __restrict__ Bv,
                const float* __restrict__ bias, void* __restrict__ Cv,
                float* __restrict__ part,
                const float* __restrict__ upt, const float* __restrict__ vpt,
                int M, int N, int K, int lda, int ldb, int ldc,
                long long sA, long long sB, long long sC,
                float alpha, int c_half, int mode, int a_f32, int b_f32)
{
    extern __shared__ __half sm[];
    __shared__ float csum[2][BN];
    const int tid = threadIdx.x;
    const int wid = tid >> 5;
    const int lane = tid & 31;
    const int g   = lane >> 2;
    const int tig = lane & 3;
    const int mw = (wid & 1) * 64;
    const int nw = (wid >> 1) * 32;

    const __half* Ah = (const __half*)Av + (a_f32 ? 0 : (long long)blockIdx.z * sA);
    const float*  Af = (const float*)Av + (a_f32 ? (long long)blockIdx.z * sA : 0);
    const __half* Bh = (const __half*)Bv + (b_f32 ? 0 : (long long)blockIdx.z * sB);
    const float*  Bf = (const float*)Bv + (b_f32 ? (long long)blockIdx.z * sB : 0);
    const int m0 = blockIdx.y * BM;
    const int n0 = blockIdx.x * BN;

    float acc[4][4][4];
#pragma unroll
    for (int mt = 0; mt < 4; mt++)
#pragma unroll
        for (int nt = 0; nt < 4; nt++)
#pragma unroll
            for (int r = 0; r < 4; r++) acc[mt][nt][r] = 0.0f;

    const uint32_t sm_base = smem_u32(sm);
    const int KT = K / BK;

    auto load_stage = [&](int p) {
        const uint32_t base = sm_base + (uint32_t)((p % STAGES) * STAGE_HALVES) * 2u;
        const uint32_t bbase = base + A_STAGE_HALVES * 2u;
        const int k0 = p * BK;
#pragma unroll
        for (int t = 0; t < 4; t++) {
            int c = tid + t * GEMM_THREADS;
            int r = c >> 3, kc = c & 7;
            const uint32_t dst = base + (uint32_t)(r * ROWH + kc * 8) * 2u;
            if (a_f32)
                ldg_f32_sts_h8(dst, Af + (long long)(m0 + r) * lda + k0 + kc * 8);
            else
                cp_async16(dst, Ah + (long long)(m0 + r) * lda + k0 + kc * 8);
        }
#pragma unroll
        for (int t = 0; t < 4; t++) {
            int c = tid + t * GEMM_THREADS;
            int r = c >> 3, kc = c & 7;
            const uint32_t dst = bbase + (uint32_t)(r * ROWH + kc * 8) * 2u;
            if (b_f32)
                ldg_f32_sts_h8(dst, Bf + (long long)(n0 + r) * ldb + k0 + kc * 8);
            else
                cp_async16(dst, Bh + (long long)(n0 + r) * ldb + k0 + kc * 8);
        }
    };

    load_stage(0); cp_commit();
    load_stage(1); cp_commit();

    const int row_a  = ((lane >> 3) & 1) * 8 + (lane & 7);
    const int kadd_a = ((lane >> 4) & 1) * 8;
    const int row_b  = ((lane >> 4) & 1) * 8 + (lane & 7);
    const int kadd_b = ((lane >> 3) & 1) * 8;

    for (int kt = 0; kt < KT; kt++) {
        cp_wait_1();
        __syncthreads();

        if (kt + 2 < KT) load_stage(kt + 2);
        cp_commit();

        const uint32_t sa  = sm_base + (uint32_t)((kt % STAGES) * STAGE_HALVES) * 2u;
        const uint32_t sbp = sa + A_STAGE_HALVES * 2u;
#pragma unroll
        for (int kk = 0; kk < 4; kk++) {
            const int k16 = kk * 16;
            uint32_t a[4][4], b[2][4];
#pragma unroll
            for (int mt = 0; mt < 4; mt++)
                ldmatrix_x4(a[mt],
                    sa + (uint32_t)((mw + mt * 16 + row_a) * ROWH + k16 + kadd_a) * 2u);
#pragma unroll
            for (int i = 0; i < 2; i++)
                ldmatrix_x4(b[i],
                    sbp + (uint32_t)((nw + i * 16 + row_b) * ROWH + k16 + kadd_b) * 2u);
#pragma unroll
            for (int mt = 0; mt < 4; mt++)
#pragma unroll
                for (int nt = 0; nt < 4; nt++)
                    mma_f16(acc[mt][nt], a[mt],
                            b[nt >> 1][(nt & 1) * 2], b[nt >> 1][(nt & 1) * 2 + 1]);
        }
    }

    if (mode == 1) {
        __half* C = (__half*)Cv + (long long)blockIdx.z * sC;
        const float* u_ = upt + (long long)blockIdx.z * SEQ;
        const float* v_ = vpt + (long long)blockIdx.z * SEQ;
        float vn0[4], vn1[4];
#pragma unroll
        for (int nt = 0; nt < 4; nt++) {
            const int n = n0 + nw + nt * 8 + 2 * tig;
            vn0[nt] = v_[n];
            vn1[nt] = v_[n + 1];
        }
        float cs0[4], cs1[4];
#pragma unroll
        for (int nt = 0; nt < 4; nt++) { cs0[nt] = 0.0f; cs1[nt] = 0.0f; }
#pragma unroll
        for (int mt = 0; mt < 4; mt++) {
            const int m = m0 + mw + mt * 16 + g;
            const float um0 = u_[m], um8 = u_[m + 8];
#pragma unroll
            for (int nt = 0; nt < 4; nt++) {
                const int n = n0 + nw + nt * 8 + 2 * tig;
                float e0 = __expf((acc[mt][nt][0] + um0 + vn0[nt]) * alpha);
                float e1 = __expf((acc[mt][nt][1] + um0 + vn1[nt]) * alpha);
                float e2 = __expf((acc[mt][nt][2] + um8 + vn0[nt]) * alpha);
                float e3 = __expf((acc[mt][nt][3] + um8 + vn1[nt]) * alpha);
                cs0[nt] += e0 + e2;
                cs1[nt] += e1 + e3;
                *(__half2*)(C + (long long)m * ldc + n)       = __floats2half2_rn(e0, e1);
                *(__half2*)(C + (long long)(m + 8) * ldc + n) = __floats2half2_rn(e2, e3);
            }
        }
#pragma unroll
        for (int msk = 4; msk <= 16; msk <<= 1) {
#pragma unroll
            for (int nt = 0; nt < 4; nt++) {
                cs0[nt] += __shfl_xor_sync(0xffffffffu, cs0[nt], msk);
                cs1[nt] += __shfl_xor_sync(0xffffffffu, cs1[nt], msk);
            }
        }
        if (g == 0) {
#pragma unroll
            for (int nt = 0; nt < 4; nt++) {
                csum[wid & 1][nw + nt * 8 + 2 * tig]     = cs0[nt];
                csum[wid & 1][nw + nt * 8 + 2 * tig + 1] = cs1[nt];
            }
        }
        __syncthreads();
        if (tid < BN)
            part[((long long)blockIdx.z * MTILES + blockIdx.y) * SEQ + n0 + tid] =
                csum[0][tid] + csum[1][tid];
        return;
    }

#pragma unroll
    for (int mt = 0; mt < 4; mt++) {
        const int m = m0 + mw + mt * 16 + g;
#pragma unroll
        for (int nt = 0; nt < 4; nt++) {
            const int n = n0 + nw + nt * 8 + 2 * tig;
            float2 v0, v1;
            v0.x = acc[mt][nt][0] * alpha;
            v0.y = acc[mt][nt][1] * alpha;
            v1.x = acc[mt][nt][2] * alpha;
            v1.y = acc[mt][nt][3] * alpha;
            if (bias) {
                float bx = bias[n], by = bias[n + 1];
                v0.x += bx; v0.y += by;
                v1.x += bx; v1.y += by;
            }
            if (c_half) {
                __half* C = (__half*)Cv + (long long)blockIdx.z * sC;
                *(__half2*)(C + (long long)m * ldc + n)       = __floats2half2_rn(v0.x, v0.y);
                *(__half2*)(C + (long long)(m + 8) * ldc + n) = __floats2half2_rn(v1.x, v1.y);
            } else {
                float* C = (float*)Cv + (long long)blockIdx.z * sC;
                *(float2*)(C + (long long)m * ldc + n)       = v0;
                *(float2*)(C + (long long)(m + 8) * ldc + n) = v1;
            }
        }
    }
}

// ---------------------------------------------------------------------------
// GEMM4: out = (1/VSCALE) * sc @ (vw * diag(invcs)) + bo    (fp32 out)
// A = sc via cp.async; B = vw LDG+scale+STS into [K,N] smem, trans fragments.
// ---------------------------------------------------------------------------
__global__ void __launch_bounds__(GEMM_THREADS, 2)
gemm4_kernel(const __half* __restrict__ A, const __half* __restrict__ Bv,
             const float* __restrict__ invcs, const float* __restrict__ bias,
             float* __restrict__ C,
             long long sA, long long sBv, long long sC)
{
    extern __shared__ __half sm[];
    const int tid = threadIdx.x;
    const int wid = tid >> 5;
    const int lane = tid & 31;
    const int g   = lane >> 2;
    const int tig = lane & 3;
    const int mw = (wid & 1) * 64;
    const int nw = (wid >> 1) * 32;

    A  += (long long)blockIdx.z * sA;
    Bv += (long long)blockIdx.z * sBv;
    const float* ics = invcs + (long long)blockIdx.z * SEQ;
    const int m0 = blockIdx.y * BM;
    const int n0 = blockIdx.x * BN;

    float acc[4][4][4];
#pragma unroll
    for (int mt = 0; mt < 4; mt++)
#pragma unroll
        for (int nt = 0; nt < 4; nt++)
#pragma unroll
            for (int r = 0; r < 4; r++) acc[mt][nt][r] = 0.0f;

    const uint32_t sm_base = smem_u32(sm);
    const int KT = SEQ / BK;                   // 32
    const int ldb = 2 * DKDIM;

    auto load_A = [&](int p) {
        const uint32_t base = sm_base + (uint32_t)((p % STAGES) * STAGE4_HALVES) * 2u;
        const int k0 = p * BK;
#pragma unroll
        for (int t = 0; t < 4; t++) {
            int c = tid + t * GEMM_THREADS;
            int r = c >> 3, kc = c & 7;
            cp_async16(base + (uint32_t)(r * ROWH + kc * 8) * 2u,
                       A + (long long)(m0 + r) * SEQ + k0 + kc * 8);
        }
    };
    auto load_B = [&](int p) {
        const uint32_t boff = (uint32_t)((p % STAGES) * STAGE4_HALVES) * 2u
                              + A_STAGE_HALVES * 2u;
        const int k0 = p * BK;
#pragma unroll
        for (int t = 0; t < 4; t++) {
            int c = tid + t * GEMM_THREADS;
            int row = c >> 4, col = (c & 15) * 8;
            float4 raw = *(const float4*)(Bv + (long long)(k0 + row) * ldb + n0 + col);
            const float s = ics[k0 + row];
            __half2* hp = (__half2*)&raw;
            float4 outv;
            __half2* op = (__half2*)&outv;
#pragma unroll
            for (int j = 0; j < 4; j++) {
                float2 f = __half22float2(hp[j]);
                op[j] = __floats2half2_rn(f.x * s, f.y * s);
            }
            *(float4*)((char*)sm + boff + (uint32_t)(row * B4_ROWH + col) * 2u) = outv;
        }
    };

    load_A(0); cp_commit();
    load_A(1); cp_commit();
    load_B(0);
    load_B(1);

    const int row_a  = ((lane >> 3) & 1) * 8 + (lane & 7);
    const int kadd_a = ((lane >> 4) & 1) * 8;
    const int row_bt = ((lane >> 3) & 1) * 8 + (lane & 7);
    const int nadd_bt = ((lane >> 4) & 1) * 8;

    for (int kt = 0; kt < KT; kt++) {
        cp_wait_1();
        __syncthreads();

        if (kt + 2 < KT) {
            load_A(kt + 2);
            load_B(kt + 2);
        }
        cp_commit();

        const uint32_t sa  = sm_base + (uint32_t)((kt % STAGES) * STAGE4_HALVES) * 2u;
        const uint32_t sbp = sa + A_STAGE_HALVES * 2u;
#pragma unroll
        for (int kk = 0; kk < 4; kk++) {
            const int k16 = kk * 16;
            uint32_t a[4][4], b[2][4];
#pragma unroll
            for (int mt = 0; mt < 4; mt++)
                ldmatrix_x4(a[mt],
                    sa + (uint32_t)((mw + mt * 16 + row_a) * ROWH + k16 + kadd_a) * 2u);
#pragma unroll
            for (int i = 0; i < 2; i++)
                ldmatrix_x4_trans(b[i],
                    sbp + (uint32_t)((k16 + row_bt) * B4_ROWH + nw + i * 16 + nadd_bt) * 2u);
#pragma unroll
            for (int mt = 0; mt < 4; mt++)
#pragma unroll
                for (int nt = 0; nt < 4; nt++)
                    mma_f16(acc[mt][nt], a[mt],
                            b[nt >> 1][(nt & 1) * 2], b[nt >> 1][(nt & 1) * 2 + 1]);
        }
    }

    float* Cp = C + (long long)blockIdx.z * sC;
#pragma unroll
    for (int mt = 0; mt < 4; mt++) {
        const int m = m0 + mw + mt * 16 + g;
#pragma unroll
        for (int nt = 0; nt < 4; nt++) {
            const int n = n0 + nw + nt * 8 + 2 * tig;
            const float bx = bias[n], by = bias[n + 1];
            float2 v0, v1;
            v0.x = acc[mt][nt][0] * (1.0f / VSCALE) + bx;
            v0.y = acc[mt][nt][1] * (1.0f / VSCALE) + by;
            v1.x = acc[mt][nt][2] * (1.0f / VSCALE) + bx;
            v1.y = acc[mt][nt][3] * (1.0f / VSCALE) + by;
            *(float2*)(Cp + (long long)m * FDIM + n)       = v0;
            *(float2*)(Cp + (long long)(m + 8) * FDIM + n) = v1;
        }
    }
}

// ---------------------------------------------------------------------------
// invcs[b,k] = VSCALE / sum_t part[b][t][k]
// ---------------------------------------------------------------------------
__global__ void __launch_bounds__(256)
invcs_kernel(const float* __restrict__ part, float* __restrict__ invcs)
{
    const int i = blockIdx.x * 256 + threadIdx.x;
    const int b = i >> 11, k = i & (SEQ - 1);
    const float* pp = part + (long long)b * MTILES * SEQ + k;
    float s = 0.0f;
#pragma unroll
    for (int tt = 0; tt < MTILES; tt++) s += pp[(long long)tt * SEQ];
    invcs[i] = VSCALE / s;
}

// ---------------------------------------------------------------------------
// Fused prep (x f2h removed — GEMMs read fp32 x directly). Dispatch:
// [0,4) b' | [4,132) w1 | [132,260) w2 | [260,264) zero | [264] c |
// [265,3337) Wq/Wk/Wv f2h | [3337,4361) Wo transpose
// ---------------------------------------------------------------------------
__global__ void __launch_bounds__(256)
prep_kernel(const float* __restrict__ Wq, const float* __restrict__ Wk,
            const float* __restrict__ Wv, const float* __restrict__ Wo,
            const float* __restrict__ bq, const float* __restrict__ bk,
            const float* __restrict__ bv,
            __half* __restrict__ gA, __half* __restrict__ gB,
            float* __restrict__ bias2,
            float* __restrict__ w1, float* __restrict__ w2,
            float* __restrict__ cc)
{
    __shared__ float t[32][33];
    const int b = blockIdx.x;
    const int tid = threadIdx.x;
    const int tx = tid & 31, ty = tid >> 5;

    if (b < 4) {
        const int f = b * 256 + tid;
        float s0 = 0.f, s1 = 0.f, s2 = 0.f, s3 = 0.f;
        float s4 = 0.f, s5 = 0.f, s6 = 0.f, s7 = 0.f;
        for (int d = 0; d < DKDIM; d += 8) {
            s0 += bv[d + 0] * Wo[(long long)(d + 0) * FDIM + f];
            s1 += bv[d + 1] * Wo[(long long)(d + 1) * FDIM + f];
            s2 += bv[d + 2] * Wo[(long long)(d + 2) * FDIM + f];
            s3 += bv[d + 3] * Wo[(long long)(d + 3) * FDIM + f];
            s4 += bv[d + 4] * Wo[(long long)(d + 4) * FDIM + f];
            s5 += bv[d + 5] * Wo[(long long)(d + 5) * FDIM + f];
            s6 += bv[d + 6] * Wo[(long long)(d + 6) * FDIM + f];
            s7 += bv[d + 7] * Wo[(long long)(d + 7) * FDIM + f];
        }
        bias2[DKDIM + f] = ((s0 + s1) + (s2 + s3)) + ((s4 + s5) + (s6 + s7));
    } else if (b < 260) {
        const int is_w2 = (b >= 132);
        const int f = ((b - (is_w2 ? 132 : 4)) << 3) + ty;
        const float* row = (is_w2 ? Wk : Wq) + (long long)f * DKDIM;
        const float* bb = is_w2 ? bq : bk;
        float s = 0.0f;
#pragma unroll
        for (int j = 0; j < DKDIM / 32; j++)
            s += row[tx + j * 32] * bb[tx + j * 32];
#pragma unroll
        for (int msk = 16; msk > 0; msk >>= 1)
            s += __shfl_xor_sync(0xffffffffu, s, msk);
        if (tx == 0) (is_w2 ? w2 : w1)[f] = s;
    } else if (b < 264) {
        bias2[(b - 260) * 256 + tid] = 0.0f;
    } else if (b == 264) {
        __shared__ float red[256];
        float s = 0.0f;
        for (int d = tid; d < DKDIM; d += 256) s += bq[d] * bk[d];
        red[tid] = s;
        __syncthreads();
        for (int off = 128; off > 0; off >>= 1) {
            if (tid < off) red[tid] += red[tid + off];
            __syncthreads();
        }
        if (tid == 0) cc[0] = red[0];
    } else if (b < 3337) {
        const int z = (b - 265) >> 10;                  // 0: Wq, 1: Wk, 2: Wv
        const float* in = (z == 0) ? Wq : (z == 1) ? Wk : Wv;
        __half* o = (z == 0) ? gB : (z == 1) ? gA : (gB + (size_t)FDIM * DKDIM);
        size_t i = (size_t)((b - 265) & 1023) * 256 + tid;
        float4 v = ((const float4*)in)[i];
        ((__half2*)o)[2 * i]     = __floats2half2_rn(v.x, v.y);
        ((__half2*)o)[2 * i + 1] = __floats2half2_rn(v.z, v.w);
    } else {
        const int tt = b - 3337;
        const int by = tt >> 5, bx = tt & 31;
        const int c0 = bx * 32, r0 = by * 32;
        __half* o = gA + (size_t)FDIM * DKDIM;
#pragma unroll
        for (int i = 0; i < 32; i += 8)
            t[ty + i][tx] = Wo[(long long)(r0 + ty + i) * FDIM + c0 + tx];
        __syncthreads();
#pragma unroll
        for (int i = 0; i < 32; i += 8)
            o[(long long)(c0 + ty + i) * DKDIM + r0 + tx] =
                __float2half_rn(t[tx][ty + i]);
    }
}

// ---------------------------------------------------------------------------
// u[i] = x[i].w1 + c ; v[i] = x[i].w2   (one warp per row)
// ---------------------------------------------------------------------------
__global__ void __launch_bounds__(256)
uv_kernel(const float* __restrict__ x, const float* __restrict__ w1,
          const float* __restrict__ w2, const float* __restrict__ cc,
          float* __restrict__ u, float* __restrict__ v)
{
    const int lane = threadIdx.x & 31;
    const int w = threadIdx.x >> 5;
    const long long i = (long long)blockIdx.x * 8 + w;
    const float* row = x + i * FDIM;
    float s1 = 0.0f, s2 = 0.0f;
#pragma unroll
    for (int j = 0; j < FDIM / 32; j++) {
        float xv = row[lane + j * 32];
        s1 += xv * w1[lane + j * 32];
        s2 += xv * w2[lane + j * 32];
    }
#pragma unroll
    for (int msk = 16; msk > 0; msk >>= 1) {
        s1 += __shfl_xor_sync(0xffffffffu, s1, msk);
        s2 += __shfl_xor_sync(0xffffffffu, s2, msk);
    }
    if (lane == 0) { u[i] = s1 + cc[0]; v[i] = s2; }
}

// ---------------------------------------------------------------------------
// Launcher
// ---------------------------------------------------------------------------
extern "C" void kernel_launch(void* const* d_in, const int* in_sizes, int n_in,
                              void* d_out, int out_size)
{
    const float* x  = (const float*)d_in[0];
    const float* Wq = (const float*)d_in[1];
    const float* bq = (const float*)d_in[2];
    const float* Wk = (const float*)d_in[3];
    const float* bk = (const float*)d_in[4];
    const float* Wv = (const float*)d_in[5];
    const float* bv = (const float*)d_in[6];
    const float* Wo = (const float*)d_in[7];
    const float* bo = (const float*)d_in[8];
    float* out = (float*)d_out;

    __half *gA, *gB, *mb, *qv, *sc;
    float *bias2, *w1, *w2, *cc, *u, *v, *part, *invcs;
    cudaGetSymbolAddress((void**)&gA,    g_gA);
    cudaGetSymbolAddress((void**)&gB,    g_gB);
    cudaGetSymbolAddress((void**)&mb,    g_mb);
    cudaGetSymbolAddress((void**)&qv,    g_qv);
    cudaGetSymbolAddress((void**)&sc,    g_sc);
    cudaGetSymbolAddress((void**)&bias2, g_bias2);
    cudaGetSymbolAddress((void**)&w1,    g_w1);
    cudaGetSymbolAddress((void**)&w2,    g_w2);
    cudaGetSymbolAddress((void**)&cc,    g_c);
    cudaGetSymbolAddress((void**)&u,     g_u);
    cudaGetSymbolAddress((void**)&v,     g_v);
    cudaGetSymbolAddress((void**)&part,  g_part);
    cudaGetSymbolAddress((void**)&invcs, g_invcs);

    cudaFuncSetAttribute(gemm_f16_kernel,
                         cudaFuncAttributeMaxDynamicSharedMemorySize, GEMM_SMEM);
    cudaFuncSetAttribute(gemm4_kernel,
                         cudaFuncAttributeMaxDynamicSharedMemorySize, GEMM4_SMEM);

    const int MS = BATCH * SEQ;                        // 8192
    const int N2 = 2 * DKDIM;                          // 2048
    const long long sQV = (long long)SEQ * N2;
    const long long sXF = (long long)SEQ * FDIM;
    const long long sSS = (long long)SEQ * SEQ;
    const long long sW  = (long long)FDIM * DKDIM;
    const float inv_sqrt_dk = 1.0f / 32.0f;

    // 0) fused prep (x f2h eliminated; small blocks first)
    prep_kernel<<<4361, 256>>>(Wq, Wk, Wv, Wo, bq, bk, bv,
                               gA, gB, bias2, w1, w2, cc);

    // 0b) batched prep GEMM: z=0: M' = Wk@Wq^T ; z=1: W'^T = Wo^T@Wv^T
    {
        dim3 grd(FDIM / BN, FDIM / BM, 2);
        gemm_f16_kernel<<<grd, GEMM_THREADS, GEMM_SMEM>>>(
            gA, gB, nullptr, mb, nullptr, nullptr, nullptr,
            FDIM, FDIM, DKDIM, DKDIM, DKDIM, FDIM, sW, sW, sW, 1.0f, 1, 0, 0, 0);
    }

    // 0c) u, v rank-1 score terms
    uv_kernel<<<MS / 8, 256>>>(x, w1, w2, cc, u, v);

    // 1) fused [qm | vw] = x @ [M' | W'^T]^T + [0 | b']  (A = fp32 x, inline cvt)
    {
        dim3 grd(N2 / BN, MS / BM, 1);
        gemm_f16_kernel<<<grd, GEMM_THREADS, GEMM_SMEM>>>(
            x, mb, bias2, qv, nullptr, nullptr, nullptr,
            MS, N2, FDIM, FDIM, FDIM, N2, 0, 0, 0, 1.0f, 1, 0, 1, 0);
    }

    // 2) sc = exp((qm x^T + u + v) / sqrt(dk)), col partial sums (B = fp32 x)
    {
        dim3 grd(SEQ / BN, SEQ / BM, BATCH);
        gemm_f16_kernel<<<grd, GEMM_THREADS, GEMM_SMEM>>>(
            qv, x, nullptr, sc, part, u, v,
            SEQ, SEQ, DKDIM, N2, FDIM, SEQ,
            sQV, sXF, sSS, inv_sqrt_dk, 1, 1, 0, 1);
    }

    // 3) invcs = VSCALE / colsum
    invcs_kernel<<<(BATCH * SEQ) / 256, 256>>>(part, invcs);

    // 4) out = (1/VSCALE) * sc @ (vw * diag(invcs)) + bo  (fp32 out; trans-B)
    {
        dim3 grd(FDIM / BN, SEQ / BM, BATCH);
        gemm4_kernel<<<grd, GEMM_THREADS, GEMM4_SMEM>>>(
            sc, qv + DKDIM, invcs, bo, out, sSS, sQV, sXF);
    }
}

// round 17
// speedup vs baseline: 1.0999x; 1.0999x over previous
#include <cuda_runtime.h>
#include <cuda_fp16.h>
#include <cstdint>
#include <math.h>

// ---------------------------------------------------------------------------
// Problem constants
// ---------------------------------------------------------------------------
#define BATCH 4
#define SEQ   2048
#define FDIM  1024
#define DKDIM 1024

// ---------------------------------------------------------------------------
// fp16 mma.sync GEMM tiling: CTA 128x128, warp 64x32, BK=64, 3 stages, 2 CTA/SM
// ---------------------------------------------------------------------------
#define BM 128
#define BN 128
#define BK 64
#define STAGES 3
#define GEMM_THREADS 256

#define ROWH 72
#define A_STAGE_HALVES (BM * ROWH)
#define B_STAGE_HALVES (BN * ROWH)
#define STAGE_HALVES   (A_STAGE_HALVES + B_STAGE_HALVES)
#define GEMM_SMEM      (STAGES * STAGE_HALVES * 2)   // 110,592 B

// GEMM4 (trans-B) layout: B tile kept [K,N] with padded rows
#define B4_ROWH 136
#define B4_STAGE_HALVES (BK * B4_ROWH)               // 8704
#define STAGE4_HALVES   (A_STAGE_HALVES + B4_STAGE_HALVES)
#define GEMM4_SMEM      (STAGES * STAGE4_HALVES * 2) // 107,520 B

#define VSCALE 64.0f
#define MTILES (SEQ / BM)

// ---------------------------------------------------------------------------
// Scratch (device globals — no dynamic allocation allowed)
// ---------------------------------------------------------------------------
__device__ __half g_gA  [(size_t)2 * FDIM * DKDIM];          // slot0: Wk, slot1: Wo^T
__device__ __half g_gB  [(size_t)2 * FDIM * DKDIM];          // slot0: Wq, slot1: Wv
__device__ __half g_mb  [(size_t)2 * DKDIM * FDIM];          // slot0: M'=WkWq^T, slot1: W'^T
__device__ __half g_qv  [(size_t)BATCH * SEQ * 2 * DKDIM];   // [qm | vw] in N
__device__ __half g_sc  [(size_t)BATCH * SEQ * SEQ];         // exp(scores)
__device__ float  g_bias2[(size_t)2 * DKDIM];                // 0 | b'=bv@Wo
__device__ float  g_w1  [FDIM];                              // Wq @ bk
__device__ float  g_w2  [FDIM];                              // Wk @ bq
__device__ float  g_c   [1];                                 // bq . bk
__device__ float  g_u   [(size_t)BATCH * SEQ];               // x.w1 + c
__device__ float  g_v   [(size_t)BATCH * SEQ];               // x.w2
__device__ float  g_part[(size_t)BATCH * MTILES * SEQ];
__device__ float  g_invcs[(size_t)BATCH * SEQ];              // VSCALE / colsum

// ---------------------------------------------------------------------------
// Helpers
// ---------------------------------------------------------------------------
__device__ __forceinline__ uint32_t smem_u32(const void* p) {
    uint32_t a;
    asm("{ .reg .u64 t; cvta.to.shared.u64 t, %1; cvt.u32.u64 %0, t; }" : "=r"(a) : "l"(p));
    return a;
}
__device__ __forceinline__ void cp_async16(uint32_t dst, const void* src) {
    asm volatile("cp.async.cg.shared.global [%0], [%1], 16;" :: "r"(dst), "l"(src) : "memory");
}
__device__ __forceinline__ void cp_commit() {
    asm volatile("cp.async.commit_group;" ::: "memory");
}
__device__ __forceinline__ void cp_wait_1() {
    asm volatile("cp.async.wait_group 1;" ::: "memory");
}
__device__ __forceinline__ void ldmatrix_x4(uint32_t* r, uint32_t addr) {
    asm volatile("ldmatrix.sync.aligned.m8n8.x4.shared.b16 {%0,%1,%2,%3}, [%4];"
                 : "=r"(r[0]), "=r"(r[1]), "=r"(r[2]), "=r"(r[3]) : "r"(addr));
}
__device__ __forceinline__ void ldmatrix_x4_trans(uint32_t* r, uint32_t addr) {
    asm volatile("ldmatrix.sync.aligned.m8n8.x4.trans.shared.b16 {%0,%1,%2,%3}, [%4];"
                 : "=r"(r[0]), "=r"(r[1]), "=r"(r[2]), "=r"(r[3]) : "r"(addr));
}
__device__ __forceinline__ void mma_f16(float* d, const uint32_t* a,
                                        uint32_t b0, uint32_t b1) {
    asm volatile(
        "mma.sync.aligned.m16n8k16.row.col.f32.f16.f16.f32 "
        "{%0,%1,%2,%3}, {%4,%5,%6,%7}, {%8,%9}, {%0,%1,%2,%3};"
        : "+f"(d[0]), "+f"(d[1]), "+f"(d[2]), "+f"(d[3])
        : "r"(a[0]), "r"(a[1]), "r"(a[2]), "r"(a[3]), "r"(b0), "r"(b1));
}
// load 8 fp32, convert RN to 8 fp16, store 16B to smem
__device__ __forceinline__ void ldg_f32_sts_h8(uint32_t dst, const float* src) {
    float4 p0 = *(const float4*)src;
    float4 p1 = *(const float4*)(src + 4);
    float4 outv;
    __half2* op = (__half2*)&outv;
    op[0] = __floats2half2_rn(p0.x, p0.y);
    op[1] = __floats2half2_rn(p0.z, p0.w);
    op[2] = __floats2half2_rn(p1.x, p1.y);
    op[3] = __floats2half2_rn(p1.z, p1.w);
    asm volatile("st.shared.v4.b32 [%0], {%1,%2,%3,%4};"
                 :: "r"(dst), "r"(((uint32_t*)&outv)[0]), "r"(((uint32_t*)&outv)[1]),
                    "r"(((uint32_t*)&outv)[2]), "r"(((uint32_t*)&outv)[3]) : "memory");
}

// ---------------------------------------------------------------------------
// fp16 tensor-core GEMM:  C = op(alpha * A * B^T + bias)
//   AF/BF (compile-time): operand is fp32 in gmem, loader converts inline (RN).
//   mode 0: plain; mode 1: C = exp((acc + u_m + v_n) * alpha), col sums -> part
// ---------------------------------------------------------------------------
template <int AF, int BF>
__global__ void __launch_bounds__(GEMM_THREADS, 2)
gemm_f16_kernel(const void* __restrict__ Av, const void* __restrict__ Bv,
                const float* __restrict__ bias, void* __restrict__ Cv,
                float* __restrict__ part,
                const float* __restrict__ upt, const float* __restrict__ vpt,
                int M, int N, int K, int lda, int ldb, int ldc,
                long long sA, long long sB, long long sC,
                float alpha, int c_half, int mode)
{
    extern __shared__ __half sm[];
    __shared__ float csum[2][BN];
    const int tid = threadIdx.x;
    const int wid = tid >> 5;
    const int lane = tid & 31;
    const int g   = lane >> 2;
    const int tig = lane & 3;
    const int mw = (wid & 1) * 64;
    const int nw = (wid >> 1) * 32;

    const __half* Ah = (const __half*)Av + (AF ? 0 : (long long)blockIdx.z * sA);
    const float*  Af = (const float*)Av + (AF ? (long long)blockIdx.z * sA : 0);
    const __half* Bh = (const __half*)Bv + (BF ? 0 : (long long)blockIdx.z * sB);
    const float*  Bf = (const float*)Bv + (BF ? (long long)blockIdx.z * sB : 0);
    const int m0 = blockIdx.y * BM;
    const int n0 = blockIdx.x * BN;

    float acc[4][4][4];
#pragma unroll
    for (int mt = 0; mt < 4; mt++)
#pragma unroll
        for (int nt = 0; nt < 4; nt++)
#pragma unroll
            for (int r = 0; r < 4; r++) acc[mt][nt][r] = 0.0f;

    const uint32_t sm_base = smem_u32(sm);
    const int KT = K / BK;

    auto load_stage = [&](int p) {
        const uint32_t base = sm_base + (uint32_t)((p % STAGES) * STAGE_HALVES) * 2u;
        const uint32_t bbase = base + A_STAGE_HALVES * 2u;
        const int k0 = p * BK;
#pragma unroll
        for (int t = 0; t < 4; t++) {
            int c = tid + t * GEMM_THREADS;
            int r = c >> 3, kc = c & 7;
            const uint32_t dst = base + (uint32_t)(r * ROWH + kc * 8) * 2u;
            if (AF)
                ldg_f32_sts_h8(dst, Af + (long long)(m0 + r) * lda + k0 + kc * 8);
            else
                cp_async16(dst, Ah + (long long)(m0 + r) * lda + k0 + kc * 8);
        }
#pragma unroll
        for (int t = 0; t < 4; t++) {
            int c = tid + t * GEMM_THREADS;
            int r = c >> 3, kc = c & 7;
            const uint32_t dst = bbase + (uint32_t)(r * ROWH + kc * 8) * 2u;
            if (BF)
                ldg_f32_sts_h8(dst, Bf + (long long)(n0 + r) * ldb + k0 + kc * 8);
            else
                cp_async16(dst, Bh + (long long)(n0 + r) * ldb + k0 + kc * 8);
        }
    };

    load_stage(0); cp_commit();
    load_stage(1); cp_commit();

    const int row_a  = ((lane >> 3) & 1) * 8 + (lane & 7);
    const int kadd_a = ((lane >> 4) & 1) * 8;
    const int row_b  = ((lane >> 4) & 1) * 8 + (lane & 7);
    const int kadd_b = ((lane >> 3) & 1) * 8;

    for (int kt = 0; kt < KT; kt++) {
        cp_wait_1();
        __syncthreads();

        if (kt + 2 < KT) load_stage(kt + 2);
        cp_commit();

        const uint32_t sa  = sm_base + (uint32_t)((kt % STAGES) * STAGE_HALVES) * 2u;
        const uint32_t sbp = sa + A_STAGE_HALVES * 2u;
#pragma unroll
        for (int kk = 0; kk < 4; kk++) {
            const int k16 = kk * 16;
            uint32_t a[4][4], b[2][4];
#pragma unroll
            for (int mt = 0; mt < 4; mt++)
                ldmatrix_x4(a[mt],
                    sa + (uint32_t)((mw + mt * 16 + row_a) * ROWH + k16 + kadd_a) * 2u);
#pragma unroll
            for (int i = 0; i < 2; i++)
                ldmatrix_x4(b[i],
                    sbp + (uint32_t)((nw + i * 16 + row_b) * ROWH + k16 + kadd_b) * 2u);
#pragma unroll
            for (int mt = 0; mt < 4; mt++)
#pragma unroll
                for (int nt = 0; nt < 4; nt++)
                    mma_f16(acc[mt][nt], a[mt],
                            b[nt >> 1][(nt & 1) * 2], b[nt >> 1][(nt & 1) * 2 + 1]);
        }
    }

    if (mode == 1) {
        __half* C = (__half*)Cv + (long long)blockIdx.z * sC;
        const float* u_ = upt + (long long)blockIdx.z * SEQ;
        const float* v_ = vpt + (long long)blockIdx.z * SEQ;
        float vn0[4], vn1[4];
#pragma unroll
        for (int nt = 0; nt < 4; nt++) {
            const int n = n0 + nw + nt * 8 + 2 * tig;
            vn0[nt] = v_[n];
            vn1[nt] = v_[n + 1];
        }
        float cs0[4], cs1[4];
#pragma unroll
        for (int nt = 0; nt < 4; nt++) { cs0[nt] = 0.0f; cs1[nt] = 0.0f; }
#pragma unroll
        for (int mt = 0; mt < 4; mt++) {
            const int m = m0 + mw + mt * 16 + g;
            const float um0 = u_[m], um8 = u_[m + 8];
#pragma unroll
            for (int nt = 0; nt < 4; nt++) {
                const int n = n0 + nw + nt * 8 + 2 * tig;
                float e0 = __expf((acc[mt][nt][0] + um0 + vn0[nt]) * alpha);
                float e1 = __expf((acc[mt][nt][1] + um0 + vn1[nt]) * alpha);
                float e2 = __expf((acc[mt][nt][2] + um8 + vn0[nt]) * alpha);
                float e3 = __expf((acc[mt][nt][3] + um8 + vn1[nt]) * alpha);
                cs0[nt] += e0 + e2;
                cs1[nt] += e1 + e3;
                *(__half2*)(C + (long long)m * ldc + n)       = __floats2half2_rn(e0, e1);
                *(__half2*)(C + (long long)(m + 8) * ldc + n) = __floats2half2_rn(e2, e3);
            }
        }
#pragma unroll
        for (int msk = 4; msk <= 16; msk <<= 1) {
#pragma unroll
            for (int nt = 0; nt < 4; nt++) {
                cs0[nt] += __shfl_xor_sync(0xffffffffu, cs0[nt], msk);
                cs1[nt] += __shfl_xor_sync(0xffffffffu, cs1[nt], msk);
            }
        }
        if (g == 0) {
#pragma unroll
            for (int nt = 0; nt < 4; nt++) {
                csum[wid & 1][nw + nt * 8 + 2 * tig]     = cs0[nt];
                csum[wid & 1][nw + nt * 8 + 2 * tig + 1] = cs1[nt];
            }
        }
        __syncthreads();
        if (tid < BN)
            part[((long long)blockIdx.z * MTILES + blockIdx.y) * SEQ + n0 + tid] =
                csum[0][tid] + csum[1][tid];
        return;
    }

#pragma unroll
    for (int mt = 0; mt < 4; mt++) {
        const int m = m0 + mw + mt * 16 + g;
#pragma unroll
        for (int nt = 0; nt < 4; nt++) {
            const int n = n0 + nw + nt * 8 + 2 * tig;
            float2 v0, v1;
            v0.x = acc[mt][nt][0] * alpha;
            v0.y = acc[mt][nt][1] * alpha;
            v1.x = acc[mt][nt][2] * alpha;
            v1.y = acc[mt][nt][3] * alpha;
            if (bias) {
                float bx = bias[n], by = bias[n + 1];
                v0.x += bx; v0.y += by;
                v1.x += bx; v1.y += by;
            }
            if (c_half) {
                __half* C = (__half*)Cv + (long long)blockIdx.z * sC;
                *(__half2*)(C + (long long)m * ldc + n)       = __floats2half2_rn(v0.x, v0.y);
                *(__half2*)(C + (long long)(m + 8) * ldc + n) = __floats2half2_rn(v1.x, v1.y);
            } else {
                float* C = (float*)Cv + (long long)blockIdx.z * sC;
                *(float2*)(C + (long long)m * ldc + n)       = v0;
                *(float2*)(C + (long long)(m + 8) * ldc + n) = v1;
            }
        }
    }
}

// ---------------------------------------------------------------------------
// GEMM4: out = (1/VSCALE) * sc @ (vw * diag(invcs)) + bo    (fp32 out)
// A = sc via cp.async; B = vw LDG+scale+STS into [K,N] smem, trans fragments.
// ---------------------------------------------------------------------------
__global__ void __launch_bounds__(GEMM_THREADS, 2)
gemm4_kernel(const __half* __restrict__ A, const __half* __restrict__ Bv,
             const float* __restrict__ invcs, const float* __restrict__ bias,
             float* __restrict__ C,
             long long sA, long long sBv, long long sC)
{
    extern __shared__ __half sm[];
    const int tid = threadIdx.x;
    const int wid = tid >> 5;
    const int lane = tid & 31;
    const int g   = lane >> 2;
    const int tig = lane & 3;
    const int mw = (wid & 1) * 64;
    const int nw = (wid >> 1) * 32;

    A  += (long long)blockIdx.z * sA;
    Bv += (long long)blockIdx.z * sBv;
    const float* ics = invcs + (long long)blockIdx.z * SEQ;
    const int m0 = blockIdx.y * BM;
    const int n0 = blockIdx.x * BN;

    float acc[4][4][4];
#pragma unroll
    for (int mt = 0; mt < 4; mt++)
#pragma unroll
        for (int nt = 0; nt < 4; nt++)
#pragma unroll
            for (int r = 0; r < 4; r++) acc[mt][nt][r] = 0.0f;

    const uint32_t sm_base = smem_u32(sm);
    const int KT = SEQ / BK;                   // 32
    const int ldb = 2 * DKDIM;

    auto load_A = [&](int p) {
        const uint32_t base = sm_base + (uint32_t)((p % STAGES) * STAGE4_HALVES) * 2u;
        const int k0 = p * BK;
#pragma unroll
        for (int t = 0; t < 4; t++) {
            int c = tid + t * GEMM_THREADS;
            int r = c >> 3, kc = c & 7;
            cp_async16(base + (uint32_t)(r * ROWH + kc * 8) * 2u,
                       A + (long long)(m0 + r) * SEQ + k0 + kc * 8);
        }
    };
    auto load_B = [&](int p) {
        const uint32_t boff = (uint32_t)((p % STAGES) * STAGE4_HALVES) * 2u
                              + A_STAGE_HALVES * 2u;
        const int k0 = p * BK;
#pragma unroll
        for (int t = 0; t < 4; t++) {
            int c = tid + t * GEMM_THREADS;
            int row = c >> 4, col = (c & 15) * 8;
            float4 raw = *(const float4*)(Bv + (long long)(k0 + row) * ldb + n0 + col);
            const float s = ics[k0 + row];
            __half2* hp = (__half2*)&raw;
            float4 outv;
            __half2* op = (__half2*)&outv;
#pragma unroll
            for (int j = 0; j < 4; j++) {
                float2 f = __half22float2(hp[j]);
                op[j] = __floats2half2_rn(f.x * s, f.y * s);
            }
            *(float4*)((char*)sm + boff + (uint32_t)(row * B4_ROWH + col) * 2u) = outv;
        }
    };

    load_A(0); cp_commit();
    load_A(1); cp_commit();
    load_B(0);
    load_B(1);

    const int row_a  = ((lane >> 3) & 1) * 8 + (lane & 7);
    const int kadd_a = ((lane >> 4) & 1) * 8;
    const int row_bt = ((lane >> 3) & 1) * 8 + (lane & 7);
    const int nadd_bt = ((lane >> 4) & 1) * 8;

    for (int kt = 0; kt < KT; kt++) {
        cp_wait_1();
        __syncthreads();

        if (kt + 2 < KT) {
            load_A(kt + 2);
            load_B(kt + 2);
        }
        cp_commit();

        const uint32_t sa  = sm_base + (uint32_t)((kt % STAGES) * STAGE4_HALVES) * 2u;
        const uint32_t sbp = sa + A_STAGE_HALVES * 2u;
#pragma unroll
        for (int kk = 0; kk < 4; kk++) {
            const int k16 = kk * 16;
            uint32_t a[4][4], b[2][4];
#pragma unroll
            for (int mt = 0; mt < 4; mt++)
                ldmatrix_x4(a[mt],
                    sa + (uint32_t)((mw + mt * 16 + row_a) * ROWH + k16 + kadd_a) * 2u);
#pragma unroll
            for (int i = 0; i < 2; i++)
                ldmatrix_x4_trans(b[i],
                    sbp + (uint32_t)((k16 + row_bt) * B4_ROWH + nw + i * 16 + nadd_bt) * 2u);
#pragma unroll
            for (int mt = 0; mt < 4; mt++)
#pragma unroll
                for (int nt = 0; nt < 4; nt++)
                    mma_f16(acc[mt][nt], a[mt],
                            b[nt >> 1][(nt & 1) * 2], b[nt >> 1][(nt & 1) * 2 + 1]);
        }
    }

    float* Cp = C + (long long)blockIdx.z * sC;
#pragma unroll
    for (int mt = 0; mt < 4; mt++) {
        const int m = m0 + mw + mt * 16 + g;
#pragma unroll
        for (int nt = 0; nt < 4; nt++) {
            const int n = n0 + nw + nt * 8 + 2 * tig;
            const float bx = bias[n], by = bias[n + 1];
            float2 v0, v1;
            v0.x = acc[mt][nt][0] * (1.0f / VSCALE) + bx;
            v0.y = acc[mt][nt][1] * (1.0f / VSCALE) + by;
            v1.x = acc[mt][nt][2] * (1.0f / VSCALE) + bx;
            v1.y = acc[mt][nt][3] * (1.0f / VSCALE) + by;
            *(float2*)(Cp + (long long)m * FDIM + n)       = v0;
            *(float2*)(Cp + (long long)(m + 8) * FDIM + n) = v1;
        }
    }
}

// ---------------------------------------------------------------------------
// invcs[b,k] = VSCALE / sum_t part[b][t][k]
// ---------------------------------------------------------------------------
__global__ void __launch_bounds__(256)
invcs_kernel(const float* __restrict__ part, float* __restrict__ invcs)
{
    const int i = blockIdx.x * 256 + threadIdx.x;
    const int b = i >> 11, k = i & (SEQ - 1);
    const float* pp = part + (long long)b * MTILES * SEQ + k;
    float s = 0.0f;
#pragma unroll
    for (int tt = 0; tt < MTILES; tt++) s += pp[(long long)tt * SEQ];
    invcs[i] = VSCALE / s;
}

// ---------------------------------------------------------------------------
// Fused prep (x f2h removed — GEMMs read fp32 x directly). Dispatch:
// [0,4) b' | [4,132) w1 | [132,260) w2 | [260,264) zero | [264] c |
// [265,3337) Wq/Wk/Wv f2h | [3337,4361) Wo transpose
// ---------------------------------------------------------------------------
__global__ void __launch_bounds__(256)
prep_kernel(const float* __restrict__ Wq, const float* __restrict__ Wk,
            const float* __restrict__ Wv, const float* __restrict__ Wo,
            const float* __restrict__ bq, const float* __restrict__ bk,
            const float* __restrict__ bv,
            __half* __restrict__ gA, __half* __restrict__ gB,
            float* __restrict__ bias2,
            float* __restrict__ w1, float* __restrict__ w2,
            float* __restrict__ cc)
{
    __shared__ float t[32][33];
    const int b = blockIdx.x;
    const int tid = threadIdx.x;
    const int tx = tid & 31, ty = tid >> 5;

    if (b < 4) {
        const int f = b * 256 + tid;
        float s0 = 0.f, s1 = 0.f, s2 = 0.f, s3 = 0.f;
        float s4 = 0.f, s5 = 0.f, s6 = 0.f, s7 = 0.f;
        for (int d = 0; d < DKDIM; d += 8) {
            s0 += bv[d + 0] * Wo[(long long)(d + 0) * FDIM + f];
            s1 += bv[d + 1] * Wo[(long long)(d + 1) * FDIM + f];
            s2 += bv[d + 2] * Wo[(long long)(d + 2) * FDIM + f];
            s3 += bv[d + 3] * Wo[(long long)(d + 3) * FDIM + f];
            s4 += bv[d + 4] * Wo[(long long)(d + 4) * FDIM + f];
            s5 += bv[d + 5] * Wo[(long long)(d + 5) * FDIM + f];
            s6 += bv[d + 6] * Wo[(long long)(d + 6) * FDIM + f];
            s7 += bv[d + 7] * Wo[(long long)(d + 7) * FDIM + f];
        }
        bias2[DKDIM + f] = ((s0 + s1) + (s2 + s3)) + ((s4 + s5) + (s6 + s7));
    } else if (b < 260) {
        const int is_w2 = (b >= 132);
        const int f = ((b - (is_w2 ? 132 : 4)) << 3) + ty;
        const float* row = (is_w2 ? Wk : Wq) + (long long)f * DKDIM;
        const float* bb = is_w2 ? bq : bk;
        float s = 0.0f;
#pragma unroll
        for (int j = 0; j < DKDIM / 32; j++)
            s += row[tx + j * 32] * bb[tx + j * 32];
#pragma unroll
        for (int msk = 16; msk > 0; msk >>= 1)
            s += __shfl_xor_sync(0xffffffffu, s, msk);
        if (tx == 0) (is_w2 ? w2 : w1)[f] = s;
    } else if (b < 264) {
        bias2[(b - 260) * 256 + tid] = 0.0f;
    } else if (b == 264) {
        __shared__ float red[256];
        float s = 0.0f;
        for (int d = tid; d < DKDIM; d += 256) s += bq[d] * bk[d];
        red[tid] = s;
        __syncthreads();
        for (int off = 128; off > 0; off >>= 1) {
            if (tid < off) red[tid] += red[tid + off];
            __syncthreads();
        }
        if (tid == 0) cc[0] = red[0];
    } else if (b < 3337) {
        const int z = (b - 265) >> 10;                  // 0: Wq, 1: Wk, 2: Wv
        const float* in = (z == 0) ? Wq : (z == 1) ? Wk : Wv;
        __half* o = (z == 0) ? gB : (z == 1) ? gA : (gB + (size_t)FDIM * DKDIM);
        size_t i = (size_t)((b - 265) & 1023) * 256 + tid;
        float4 v = ((const float4*)in)[i];
        ((__half2*)o)[2 * i]     = __floats2half2_rn(v.x, v.y);
        ((__half2*)o)[2 * i + 1] = __floats2half2_rn(v.z, v.w);
    } else {
        const int tt = b - 3337;
        const int by = tt >> 5, bx = tt & 31;
        const int c0 = bx * 32, r0 = by * 32;
        __half* o = gA + (size_t)FDIM * DKDIM;
#pragma unroll
        for (int i = 0; i < 32; i += 8)
            t[ty + i][tx] = Wo[(long long)(r0 + ty + i) * FDIM + c0 + tx];
        __syncthreads();
#pragma unroll
        for (int i = 0; i < 32; i += 8)
            o[(long long)(c0 + ty + i) * DKDIM + r0 + tx] =
                __float2half_rn(t[tx][ty + i]);
    }
}

// ---------------------------------------------------------------------------
// u[i] = x[i].w1 + c ; v[i] = x[i].w2   (one warp per row)
// ---------------------------------------------------------------------------
__global__ void __launch_bounds__(256)
uv_kernel(const float* __restrict__ x, const float* __restrict__ w1,
          const float* __restrict__ w2, const float* __restrict__ cc,
          float* __restrict__ u, float* __restrict__ v)
{
    const int lane = threadIdx.x & 31;
    const int w = threadIdx.x >> 5;
    const long long i = (long long)blockIdx.x * 8 + w;
    const float* row = x + i * FDIM;
    float s1 = 0.0f, s2 = 0.0f;
#pragma unroll
    for (int j = 0; j < FDIM / 32; j++) {
        float xv = row[lane + j * 32];
        s1 += xv * w1[lane + j * 32];
        s2 += xv * w2[lane + j * 32];
    }
#pragma unroll
    for (int msk = 16; msk > 0; msk >>= 1) {
        s1 += __shfl_xor_sync(0xffffffffu, s1, msk);
        s2 += __shfl_xor_sync(0xffffffffu, s2, msk);
    }
    if (lane == 0) { u[i] = s1 + cc[0]; v[i] = s2; }
}

// ---------------------------------------------------------------------------
// Launcher
// ---------------------------------------------------------------------------
extern "C" void kernel_launch(void* const* d_in, const int* in_sizes, int n_in,
                              void* d_out, int out_size)
{
    const float* x  = (const float*)d_in[0];
    const float* Wq = (const float*)d_in[1];
    const float* bq = (const float*)d_in[2];
    const float* Wk = (const float*)d_in[3];
    const float* bk = (const float*)d_in[4];
    const float* Wv = (const float*)d_in[5];
    const float* bv = (const float*)d_in[6];
    const float* Wo = (const float*)d_in[7];
    const float* bo = (const float*)d_in[8];
    float* out = (float*)d_out;

    __half *gA, *gB, *mb, *qv, *sc;
    float *bias2, *w1, *w2, *cc, *u, *v, *part, *invcs;
    cudaGetSymbolAddress((void**)&gA,    g_gA);
    cudaGetSymbolAddress((void**)&gB,    g_gB);
    cudaGetSymbolAddress((void**)&mb,    g_mb);
    cudaGetSymbolAddress((void**)&qv,    g_qv);
    cudaGetSymbolAddress((void**)&sc,    g_sc);
    cudaGetSymbolAddress((void**)&bias2, g_bias2);
    cudaGetSymbolAddress((void**)&w1,    g_w1);
    cudaGetSymbolAddress((void**)&w2,    g_w2);
    cudaGetSymbolAddress((void**)&cc,    g_c);
    cudaGetSymbolAddress((void**)&u,     g_u);
    cudaGetSymbolAddress((void**)&v,     g_v);
    cudaGetSymbolAddress((void**)&part,  g_part);
    cudaGetSymbolAddress((void**)&invcs, g_invcs);

    cudaFuncSetAttribute(gemm_f16_kernel<0, 0>,
                         cudaFuncAttributeMaxDynamicSharedMemorySize, GEMM_SMEM);
    cudaFuncSetAttribute(gemm_f16_kernel<1, 0>,
                         cudaFuncAttributeMaxDynamicSharedMemorySize, GEMM_SMEM);
    cudaFuncSetAttribute(gemm_f16_kernel<0, 1>,
                         cudaFuncAttributeMaxDynamicSharedMemorySize, GEMM_SMEM);
    cudaFuncSetAttribute(gemm4_kernel,
                         cudaFuncAttributeMaxDynamicSharedMemorySize, GEMM4_SMEM);

    const int MS = BATCH * SEQ;                        // 8192
    const int N2 = 2 * DKDIM;                          // 2048
    const long long sQV = (long long)SEQ * N2;
    const long long sXF = (long long)SEQ * FDIM;
    const long long sSS = (long long)SEQ * SEQ;
    const long long sW  = (long long)FDIM * DKDIM;
    const float inv_sqrt_dk = 1.0f / 32.0f;

    // 0) fused prep (x f2h eliminated; small blocks first)
    prep_kernel<<<4361, 256>>>(Wq, Wk, Wv, Wo, bq, bk, bv,
                               gA, gB, bias2, w1, w2, cc);

    // 0b) batched prep GEMM: z=0: M' = Wk@Wq^T ; z=1: W'^T = Wo^T@Wv^T
    {
        dim3 grd(FDIM / BN, FDIM / BM, 2);
        gemm_f16_kernel<0, 0><<<grd, GEMM_THREADS, GEMM_SMEM>>>(
            gA, gB, nullptr, mb, nullptr, nullptr, nullptr,
            FDIM, FDIM, DKDIM, DKDIM, DKDIM, FDIM, sW, sW, sW, 1.0f, 1, 0);
    }

    // 0c) u, v rank-1 score terms
    uv_kernel<<<MS / 8, 256>>>(x, w1, w2, cc, u, v);

    // 1) fused [qm | vw] = x @ [M' | W'^T]^T + [0 | b']  (A = fp32 x, inline cvt)
    {
        dim3 grd(N2 / BN, MS / BM, 1);
        gemm_f16_kernel<1, 0><<<grd, GEMM_THREADS, GEMM_SMEM>>>(
            x, mb, bias2, qv, nullptr, nullptr, nullptr,
            MS, N2, FDIM, FDIM, FDIM, N2, 0, 0, 0, 1.0f, 1, 0);
    }

    // 2) sc = exp((qm x^T + u + v) / sqrt(dk)), col partial sums (B = fp32 x)
    {
        dim3 grd(SEQ / BN, SEQ / BM, BATCH);
        gemm_f16_kernel<0, 1><<<grd, GEMM_THREADS, GEMM_SMEM>>>(
            qv, x, nullptr, sc, part, u, v,
            SEQ, SEQ, DKDIM, N2, FDIM, SEQ,
            sQV, sXF, sSS, inv_sqrt_dk, 1, 1);
    }

    // 3) invcs = VSCALE / colsum
    invcs_kernel<<<(BATCH * SEQ) / 256, 256>>>(part, invcs);

    // 4) out = (1/VSCALE) * sc @ (vw * diag(invcs)) + bo  (fp32 out; trans-B)
    {
        dim3 grd(FDIM / BN, SEQ / BM, BATCH);
        gemm4_kernel<<<grd, GEMM_THREADS, GEMM4_SMEM>>>(
            sc, qv + DKDIM, invcs, bo, out, sSS, sQV, sXF);
    }
}